// round 15
// baseline (speedup 1.0000x reference)
#include <cuda_runtime.h>
#include <cuda_bf16.h>
#include <cstdint>

// ---------------- problem constants ----------------
#define TT   4
#define BB   16
#define CC   512
#define NN   256
#define HID  2048
#define TBCN (TT*BB*CC*NN)     // 8,388,608

// ---------------- static scratch ----------------
__device__ float         g_xt  [64L*256*512];    // x transposed, channels-last fp32
__device__ __nv_bfloat16 g_sx  [64L*256*512];    // spikes (x / mlp), bf16
__device__ __nv_bfloat16 g_qs  [64L*256*1536];   // qkv spikes bf16 (att in place in q cols)
__device__ float         g_xat [64L*256*512];    // attention block output fp32
__device__ __nv_bfloat16 g_h1s [64L*256*2048];   // fc1 spikes bf16
__device__ __nv_bfloat16 g_kvs [64*512];         // kv spikes bf16
__device__ int           g_kvcnt[64*512];        // kv AND-counts (int, exact)
__device__ unsigned int  g_kvdone;               // kvcount completion counter
__device__ __nv_bfloat16 g_whi [3145728];        // weights hi bf16: qkv|proj|fc1|fc2
__device__ __nv_bfloat16 g_wlo [3145728];        // weights lo bf16
__device__ float         g_A   [4608];           // folded BN scale
__device__ float         g_Bc  [4608];           // folded BN bias

#define W_QKV  0L
#define W_PROJ 786432L
#define W_FC1  1048576L
#define W_FC2  2097152L

#define BF1 ((unsigned short)0x3F80)

// ---------------- PTX helpers (baseline ISA only) ----------------
__device__ __forceinline__ uint32_t smem_u32(const void* p) {
    uint32_t a;
    asm("{ .reg .u64 t; cvta.to.shared.u64 t, %1; cvt.u32.u64 %0, t; }" : "=r"(a) : "l"(p));
    return a;
}
__device__ __forceinline__ void cp16(uint32_t dst, const void* src) {
    asm volatile("cp.async.cg.shared.global [%0], [%1], 16;" :: "r"(dst), "l"(src));
}
#define CP_COMMIT() asm volatile("cp.async.commit_group;" ::: "memory")
#define CP_WAIT0()  asm volatile("cp.async.wait_group 0;" ::: "memory")

__device__ __forceinline__ void ldm4(uint32_t& r0, uint32_t& r1, uint32_t& r2, uint32_t& r3,
                                     uint32_t addr) {
    asm volatile("ldmatrix.sync.aligned.m8n8.x4.shared.b16 {%0,%1,%2,%3}, [%4];"
                 : "=r"(r0), "=r"(r1), "=r"(r2), "=r"(r3) : "r"(addr));
}
__device__ __forceinline__ void mma16816(float* c, const uint32_t* a, uint32_t b0, uint32_t b1) {
    asm volatile("mma.sync.aligned.m16n8k16.row.col.f32.bf16.bf16.f32 "
                 "{%0,%1,%2,%3}, {%4,%5,%6,%7}, {%8,%9}, {%0,%1,%2,%3};"
                 : "+f"(c[0]), "+f"(c[1]), "+f"(c[2]), "+f"(c[3])
                 : "r"(a[0]), "r"(a[1]), "r"(a[2]), "r"(a[3]), "r"(b0), "r"(b1));
}
__device__ __forceinline__ unsigned short bfbits(float f) {
    __nv_bfloat16 h = __float2bfloat16(f);
    return *(unsigned short*)&h;
}

// SMEM: per stage A(128x144B) | Bhi(128x144B) | Blo(128x144B); 2 stages; K-chunk 64
#define RS    144
#define STG_A (128*RS)        // 18432
#define STAGE (3*STG_A)       // 55296
#define SMEM_TOT (2*STAGE)    // 110592  (x2 CTAs/SM)

// ---------------- merged prep kernel ----------------
// blocks [0,18): BN fold; [18,3090): weight split (x4 vectorized);
// [3090,3218): zero kvcnt (+done flag); [3218,5266): transpose + shortcut LIF of x
__global__ void prep_kernel(const float* __restrict__ qbn, const float* __restrict__ kbn,
                            const float* __restrict__ vbn, const float* __restrict__ pbn,
                            const float* __restrict__ f1bn, const float* __restrict__ f2bn,
                            const float* __restrict__ pb, const float* __restrict__ f1b,
                            const float* __restrict__ f2b,
                            const float* __restrict__ qw, const float* __restrict__ kw,
                            const float* __restrict__ vw, const float* __restrict__ pj,
                            const float* __restrict__ f1, const float* __restrict__ f2,
                            const float* __restrict__ x)
{
    int blk = blockIdx.x;
    if (blk < 18) {
        int i = blk * 256 + threadIdx.x;
        if (i >= 4608) return;
        const float* bn; int c; int nc; float bias = 0.f;
        if (i < 1536)      { int s = i >> 9; c = i & 511; nc = CC;
                             bn = (s == 0) ? qbn : (s == 1) ? kbn : vbn; }
        else if (i < 2048) { c = i - 1536; nc = CC;  bn = pbn;  bias = pb[c]; }
        else if (i < 4096) { c = i - 2048; nc = HID; bn = f1bn; bias = f1b[c]; }
        else               { c = i - 4096; nc = CC;  bn = f2bn; bias = f2b[c]; }
        float g  = bn[c];
        float be = bn[nc + c];
        float m  = bn[2*nc + c];
        float v  = bn[3*nc + c];
        float a  = g / sqrtf(v + 1e-5f);
        g_A[i]  = a;
        g_Bc[i] = be + (bias - m) * a;
    } else if (blk < 3090) {
        long i4 = (long)(blk - 18) * 256 + threadIdx.x;   // float4 index, 0..786431
        long i  = i4 * 4;
        float4 w4;
        if (i < 786432L)       { long s = i / 262144L, r = i % 262144L;
                                 const float* src = (s == 0) ? qw : (s == 1) ? kw : vw;
                                 w4 = *(const float4*)(src + r); }
        else if (i < 1048576L) w4 = *(const float4*)(pj + i - 786432L);
        else if (i < 2097152L) w4 = *(const float4*)(f1 + i - 1048576L);
        else                   w4 = *(const float4*)(f2 + i - 2097152L);
        ushort4 hv, lv;
        hv.x = bfbits(w4.x); lv.x = bfbits(w4.x - __bfloat162float(__float2bfloat16(w4.x)));
        hv.y = bfbits(w4.y); lv.y = bfbits(w4.y - __bfloat162float(__float2bfloat16(w4.y)));
        hv.z = bfbits(w4.z); lv.z = bfbits(w4.z - __bfloat162float(__float2bfloat16(w4.z)));
        hv.w = bfbits(w4.w); lv.w = bfbits(w4.w - __bfloat162float(__float2bfloat16(w4.w)));
        *(ushort4*)((unsigned short*)g_whi + i) = hv;
        *(ushort4*)((unsigned short*)g_wlo + i) = lv;
    } else if (blk < 3218) {
        int i = (blk - 3090) * 256 + threadIdx.x;
        g_kvcnt[i] = 0;
        if (blk == 3090 && threadIdx.x == 0) g_kvdone = 0;
    } else {
        __shared__ float t4[4][32][33];
        int idx = blk - 3218;
        int n0 = (idx & 7) * 32;
        int c0 = ((idx >> 3) & 15) * 32;
        int b  = idx >> 7;
        int tx = threadIdx.x & 31, ty = threadIdx.x >> 5;
#pragma unroll
        for (int t = 0; t < TT; t++)
#pragma unroll
            for (int i = 0; i < 4; i++) {
                int c = c0 + ty + i * 8;
                t4[t][ty + i * 8][tx] = x[(((long)t * BB + b) * CC + c) * NN + n0 + tx];
            }
        __syncthreads();
#pragma unroll
        for (int i = 0; i < 4; i++) {
            int n = n0 + ty + i * 8;
            int c = c0 + tx;
            float v = 0.f;
#pragma unroll
            for (int t = 0; t < TT; t++) {
                float xv = t4[t][tx][ty + i * 8];
                long o = (((long)t * BB + b) * NN + n) * CC + c;
                g_xt[o] = xv;
                v = 0.5f * (v + xv);
                bool sp = (v >= 1.0f);
                g_sx[o] = __float2bfloat16(sp ? 1.f : 0.f);
                if (sp) v = 0.f;
            }
        }
    }
}

// coalesced kv AND-count + fused talking-heads LIF (last-block pattern)
__global__ void kvcount_kernel()
{
    int tb = blockIdx.x >> 4;
    int ng = blockIdx.x & 15;
    int t  = threadIdx.x;
    const unsigned int* qs = (const unsigned int*)g_qs;
    long base = (long)tb * 256 * 768;
    int c0 = 0, c1 = 0;
#pragma unroll 8
    for (int n = ng * 16; n < ng * 16 + 16; n++) {
        unsigned int k = qs[base + (long)n * 768 + 256 + t];
        unsigned int v = qs[base + (long)n * 768 + 512 + t];
        unsigned int a = k & v;
        c0 += (a & 0xFFFFu) ? 1 : 0;
        c1 += (a >> 16)     ? 1 : 0;
    }
    atomicAdd(&g_kvcnt[tb * 512 + 2 * t],     c0);
    atomicAdd(&g_kvcnt[tb * 512 + 2 * t + 1], c1);

    // last block computes the talking-heads LIF over the completed counts
    __threadfence();
    __shared__ bool is_last;
    if (threadIdx.x == 0) {
        unsigned int done = atomicAdd(&g_kvdone, 1u);
        is_last = (done == gridDim.x - 1);
    }
    __syncthreads();
    if (is_last) {
#pragma unroll 4
        for (int j = 0; j < 32; j++) {
            int idx = j * 256 + threadIdx.x;    // 0..8191 = b*512 + c
            int b = idx >> 9, c = idx & 511;
            float v = 0.f;
#pragma unroll
            for (int tt = 0; tt < TT; tt++) {
                int tbb = tt * BB + b;
                float s = (float)g_kvcnt[tbb * 512 + c];
                v = 0.5f * (v + s);
                bool sp = (v >= 0.5f);
                g_kvs[tbb * 512 + c] = __float2bfloat16(sp ? 1.f : 0.f);
                if (sp) v = 0.f;
            }
        }
    }
}

// att = q & kv (bitwise over bf16 spike lanes, 8 lanes/thread), in place
__global__ void att_kernel()
{
    long i = (long)blockIdx.x * 256 + threadIdx.x;      // uint4 groups over 64*256*512
    int c8 = (int)(i & 63);
    int n  = (int)((i >> 6) & 255);
    int tb = (int)(i >> 14);
    long qi = (((long)tb * 256 + n) * 1536 + c8 * 8) >> 3;   // uint4 index (8 bf16)
    uint4 q = ((uint4*)g_qs)[qi];
    uint4 kv = ((const uint4*)g_kvs)[((long)tb * 512 + c8 * 8) >> 3];
    q.x &= kv.x; q.y &= kv.y; q.z &= kv.z; q.w &= kv.w;
    ((uint4*)g_qs)[qi] = q;
}

// ---------------- HMMA GEMM with fused LIF epilogue ----------------
// Tile: M = 128 rows = 32 spatial x 4 timesteps, N = 128 channels, grid (NN/32, MC/128, BB).
__global__ void __launch_bounds__(256, 2)
mma_lif(const __nv_bfloat16* __restrict__ A, int lda,
        const __nv_bfloat16* __restrict__ Whi, const __nv_bfloat16* __restrict__ Wlo,
        long wbase, int K,
        const float* __restrict__ Asc, const float* __restrict__ Bsc,
        const float* __restrict__ Res,           // fp32 [tb][n][MC] or null
        float* __restrict__ OutF,                // fp32 [tb][n][MC] or null
        __nv_bfloat16* __restrict__ OutS,        // spikes [tb][n][MC]
        int MC,
        float* __restrict__ vh)                  // fp32 vh or null (qkv only)
{
    extern __shared__ char sm[];
    const uint32_t smb = smem_u32(sm);

    const int tid  = threadIdx.x;
    const int lane = tid & 31;
    const int wid  = tid >> 5;
    const int wm   = wid & 1;
    const int wn   = wid >> 1;
    const int n0   = blockIdx.x * 32;   // spatial
    const int c0   = blockIdx.y * 128;  // channels
    const int b    = blockIdx.z;
    const int nch  = K >> 6;

    const __nv_bfloat16* Ab = A + ((long)b * 256 + n0) * lda;
    const __nv_bfloat16* Hb = Whi + wbase + (long)c0 * K;
    const __nv_bfloat16* Lb = Wlo + wbase + (long)c0 * K;

    const int arow = (lane & 7) + ((lane >> 3) & 1) * 8;
    const int ac8  = (lane >> 4) * 16;
    const int brow = (lane & 7) + (lane >> 4) * 8;
    const int bc8  = ((lane >> 3) & 1) * 16;

    float acc[4][4][4];
#pragma unroll
    for (int a_ = 0; a_ < 4; a_++)
#pragma unroll
        for (int b_ = 0; b_ < 4; b_++)
#pragma unroll
            for (int r_ = 0; r_ < 4; r_++) acc[a_][b_][r_] = 0.f;

    auto load_stage = [&](int s, int kc) {
        uint32_t base = smb + s * STAGE;
#pragma unroll
        for (int jj = 0; jj < 4; jj++) {
            int u = jj * 256 + tid;
            int r = u >> 3, c16 = u & 7;
            long grow = (long)(r >> 5) * 4096 + (r & 31);   // t*BB*256 + nl rows
            cp16(base + r * RS + c16 * 16, Ab + grow * lda + kc * 64 + c16 * 8);
        }
#pragma unroll
        for (int jj = 0; jj < 4; jj++) {
            int u = jj * 256 + tid;
            int r = u >> 3, c16 = u & 7;
            cp16(base + STG_A + r * RS + c16 * 16, Hb + (long)r * K + kc * 64 + c16 * 8);
        }
#pragma unroll
        for (int jj = 0; jj < 4; jj++) {
            int u = jj * 256 + tid;
            int r = u >> 3, c16 = u & 7;
            cp16(base + 2 * STG_A + r * RS + c16 * 16, Lb + (long)r * K + kc * 64 + c16 * 8);
        }
    };

    load_stage(0, 0);
    CP_COMMIT();

    for (int ch = 0; ch < nch; ch++) {
        CP_WAIT0();
        __syncthreads();
        if (ch + 1 < nch) { load_stage((ch + 1) & 1, ch + 1); CP_COMMIT(); }

        const int s = ch & 1;
        const uint32_t ab = smb + s * STAGE;
        const uint32_t hb = ab + STG_A;
        const uint32_t lb = hb + STG_A;

#pragma unroll
        for (int kt = 0; kt < 4; kt++) {
            const int ko = kt * 32;
            uint32_t a[4][4];
#pragma unroll
            for (int mt = 0; mt < 4; mt++)
                ldm4(a[mt][0], a[mt][1], a[mt][2], a[mt][3],
                     ab + (mt * 32 + wm * 16 + arow) * RS + ko + ac8);

            uint32_t bh[8], bl[8];
#pragma unroll
            for (int p = 0; p < 2; p++)
                ldm4(bh[p*4+0], bh[p*4+1], bh[p*4+2], bh[p*4+3],
                     hb + (wn * 32 + p * 16 + brow) * RS + ko + bc8);
#pragma unroll
            for (int g = 0; g < 2; g++) {
                int bi = (g >> 1) * 4 + (g & 1) * 2;
#pragma unroll
                for (int mt = 0; mt < 4; mt++)
                    mma16816(acc[mt][g], a[mt], bh[bi], bh[bi + 1]);
            }
#pragma unroll
            for (int p = 0; p < 2; p++)
                ldm4(bl[p*4+0], bl[p*4+1], bl[p*4+2], bl[p*4+3],
                     lb + (wn * 32 + p * 16 + brow) * RS + ko + bc8);
#pragma unroll
            for (int g = 2; g < 4; g++) {
                int bi = (g >> 1) * 4 + (g & 1) * 2;
#pragma unroll
                for (int mt = 0; mt < 4; mt++)
                    mma16816(acc[mt][g], a[mt], bh[bi], bh[bi + 1]);
            }
#pragma unroll
            for (int g = 0; g < 4; g++) {
                int bi = (g >> 1) * 4 + (g & 1) * 2;
#pragma unroll
                for (int mt = 0; mt < 4; mt++)
                    mma16816(acc[mt][g], a[mt], bl[bi], bl[bi + 1]);
            }
        }
    }

    // ---------------- fused LIF epilogue ----------------
#pragma unroll
    for (int g = 0; g < 4; g++) {
        int col = c0 + wn * 32 + g * 8 + (lane & 3) * 2;
        float sA0 = Asc[col], sA1 = Asc[col + 1];
        float sB0 = Bsc[col], sB1 = Bsc[col + 1];
        bool dv = (vh != nullptr) && (col >= 1024);
        int h = 0, chv = 0;
        if (dv) { h = (col - 1024) >> 6; chv = (col - 1024) & 63; }
#pragma unroll
        for (int rv = 0; rv < 2; rv++) {
            int n = n0 + wm * 16 + (lane >> 2) + rv * 8;
            float v0 = 0.f, v1 = 0.f;
#pragma unroll
            for (int mt = 0; mt < 4; mt++) {
                long rowb = (long)(mt * BB + b) * 256 + n;
                float x0 = acc[mt][g][rv * 2 + 0] * sA0 + sB0;
                float x1 = acc[mt][g][rv * 2 + 1] * sA1 + sB1;
                if (Res) {
                    float2 rr = *(const float2*)(Res + rowb * MC + col);
                    x0 += rr.x; x1 += rr.y;
                }
                if (OutF) {
                    float2 w; w.x = x0; w.y = x1;
                    *(float2*)(OutF + rowb * MC + col) = w;
                }
                v0 = 0.5f * (v0 + x0);
                v1 = 0.5f * (v1 + x1);
                bool s0 = (v0 >= 1.0f), s1 = (v1 >= 1.0f);
                if (s0) v0 = 0.f;
                if (s1) v1 = 0.f;
                ushort2 sp;
                sp.x = s0 ? BF1 : 0;
                sp.y = s1 ? BF1 : 0;
                *(ushort2*)(OutS + rowb * MC + col) = sp;
                if (dv) {
                    float2 vo;
                    vo.x = s0 ? 1.f : 0.f;
                    vo.y = s1 ? 1.f : 0.f;
                    *(float2*)(vh + (((long)(mt * BB + b) * 8 + h) * 256 + n) * 64 + chv) = vo;
                }
            }
        }
    }
}

// ---------------- HMMA GEMM (fc2: channel-major out + residual) ----------------
__global__ void __launch_bounds__(256, 2)
mma_gemm(const __nv_bfloat16* __restrict__ A, long a_bs, int lda,
         const __nv_bfloat16* __restrict__ Whi, const __nv_bfloat16* __restrict__ Wlo,
         long wbase, int K,
         const float* __restrict__ Asc, const float* __restrict__ Bsc,
         const float* __restrict__ Res, long res_bs,
         float* __restrict__ Out, long out_bs, int Mout)
{
    extern __shared__ char sm[];
    const uint32_t smb = smem_u32(sm);

    const int tid  = threadIdx.x;
    const int lane = tid & 31;
    const int wid  = tid >> 5;
    const int wm   = wid & 1;
    const int wn   = wid >> 1;
    const int n0   = blockIdx.x * 128;
    const int c0   = blockIdx.y * 128;
    const int tb   = blockIdx.z;
    const int nch  = K >> 6;

    const __nv_bfloat16* Ab = A + (long)tb * a_bs + (long)n0 * lda;
    const __nv_bfloat16* Hb = Whi + wbase + (long)c0 * K;
    const __nv_bfloat16* Lb = Wlo + wbase + (long)c0 * K;

    const int arow = (lane & 7) + ((lane >> 3) & 1) * 8;
    const int ac8  = (lane >> 4) * 16;
    const int brow = (lane & 7) + (lane >> 4) * 8;
    const int bc8  = ((lane >> 3) & 1) * 16;

    float acc[4][4][4];
#pragma unroll
    for (int a_ = 0; a_ < 4; a_++)
#pragma unroll
        for (int b_ = 0; b_ < 4; b_++)
#pragma unroll
            for (int r_ = 0; r_ < 4; r_++) acc[a_][b_][r_] = 0.f;

    auto load_stage = [&](int s, int kc) {
        uint32_t base = smb + s * STAGE;
#pragma unroll
        for (int jj = 0; jj < 4; jj++) {
            int u = jj * 256 + tid;
            int r = u >> 3, c16 = u & 7;
            cp16(base + r * RS + c16 * 16, Ab + (long)r * lda + kc * 64 + c16 * 8);
        }
#pragma unroll
        for (int jj = 0; jj < 4; jj++) {
            int u = jj * 256 + tid;
            int r = u >> 3, c16 = u & 7;
            cp16(base + STG_A + r * RS + c16 * 16, Hb + (long)r * K + kc * 64 + c16 * 8);
        }
#pragma unroll
        for (int jj = 0; jj < 4; jj++) {
            int u = jj * 256 + tid;
            int r = u >> 3, c16 = u & 7;
            cp16(base + 2 * STG_A + r * RS + c16 * 16, Lb + (long)r * K + kc * 64 + c16 * 8);
        }
    };

    load_stage(0, 0);
    CP_COMMIT();

    for (int ch = 0; ch < nch; ch++) {
        CP_WAIT0();
        __syncthreads();
        if (ch + 1 < nch) { load_stage((ch + 1) & 1, ch + 1); CP_COMMIT(); }

        const int s = ch & 1;
        const uint32_t ab = smb + s * STAGE;
        const uint32_t hb = ab + STG_A;
        const uint32_t lb = hb + STG_A;

#pragma unroll
        for (int kt = 0; kt < 4; kt++) {
            const int ko = kt * 32;
            uint32_t a[4][4];
#pragma unroll
            for (int mt = 0; mt < 4; mt++)
                ldm4(a[mt][0], a[mt][1], a[mt][2], a[mt][3],
                     ab + (wm * 64 + mt * 16 + arow) * RS + ko + ac8);

            uint32_t bh[8], bl[8];
#pragma unroll
            for (int p = 0; p < 2; p++)
                ldm4(bh[p*4+0], bh[p*4+1], bh[p*4+2], bh[p*4+3],
                     hb + (wn * 32 + p * 16 + brow) * RS + ko + bc8);
#pragma unroll
            for (int g = 0; g < 2; g++) {
                int bi = (g >> 1) * 4 + (g & 1) * 2;
#pragma unroll
                for (int mt = 0; mt < 4; mt++)
                    mma16816(acc[mt][g], a[mt], bh[bi], bh[bi + 1]);
            }
#pragma unroll
            for (int p = 0; p < 2; p++)
                ldm4(bl[p*4+0], bl[p*4+1], bl[p*4+2], bl[p*4+3],
                     lb + (wn * 32 + p * 16 + brow) * RS + ko + bc8);
#pragma unroll
            for (int g = 2; g < 4; g++) {
                int bi = (g >> 1) * 4 + (g & 1) * 2;
#pragma unroll
                for (int mt = 0; mt < 4; mt++)
                    mma16816(acc[mt][g], a[mt], bh[bi], bh[bi + 1]);
            }
#pragma unroll
            for (int g = 0; g < 4; g++) {
                int bi = (g >> 1) * 4 + (g & 1) * 2;
#pragma unroll
                for (int mt = 0; mt < 4; mt++)
                    mma16816(acc[mt][g], a[mt], bl[bi], bl[bi + 1]);
            }
        }
    }
    __syncthreads();

    // channel-major epilogue: stage through smem for coalesced stores
    float* sf = (float*)sm;
#pragma unroll
    for (int mt = 0; mt < 4; mt++) {
#pragma unroll
        for (int g = 0; g < 4; g++) {
            int cl = wn * 32 + g * 8 + (lane & 3) * 2;
            int rl = wm * 64 + mt * 16 + (lane >> 2);
            int col = c0 + cl, row = n0 + rl;
            float sA0 = Asc[col], sA1 = Asc[col + 1];
            float sB0 = Bsc[col], sB1 = Bsc[col + 1];
            float v00 = acc[mt][g][0] * sA0 + sB0;
            float v01 = acc[mt][g][1] * sA1 + sB1;
            float v10 = acc[mt][g][2] * sA0 + sB0;
            float v11 = acc[mt][g][3] * sA1 + sB1;
            const float* r0 = Res + (long)tb * res_bs + (long)row * Mout + col;
            float2 ra = *(const float2*)r0;
            float2 rb = *(const float2*)(r0 + 8 * Mout);
            v00 += ra.x; v01 += ra.y; v10 += rb.x; v11 += rb.y;
            sf[cl * 132 + rl]           = v00;
            sf[(cl + 1) * 132 + rl]     = v01;
            sf[cl * 132 + rl + 8]       = v10;
            sf[(cl + 1) * 132 + rl + 8] = v11;
        }
    }
    __syncthreads();
#pragma unroll
    for (int i = 0; i < 16; i++) {
        int c = wid * 16 + i;
        float* orow = Out + (long)tb * out_bs + (long)(c0 + c) * NN + n0;
#pragma unroll
        for (int j = 0; j < 4; j++)
            orow[lane + j * 32] = sf[c * 132 + lane + j * 32];
    }
}

// ---------------- launch ----------------
extern "C" void kernel_launch(void* const* d_in, const int* in_sizes, int n_in,
                              void* d_out, int out_size)
{
    const float* x      = (const float*)d_in[0];
    const float* q_w    = (const float*)d_in[1];
    const float* k_w    = (const float*)d_in[2];
    const float* v_w    = (const float*)d_in[3];
    const float* proj_w = (const float*)d_in[4];
    const float* proj_b = (const float*)d_in[5];
    const float* fc1_w  = (const float*)d_in[6];
    const float* fc1_b  = (const float*)d_in[7];
    const float* fc2_w  = (const float*)d_in[8];
    const float* fc2_b  = (const float*)d_in[9];
    const float* q_bn   = (const float*)d_in[10];
    const float* k_bn   = (const float*)d_in[11];
    const float* v_bn   = (const float*)d_in[12];
    const float* proj_bn= (const float*)d_in[13];
    const float* fc1_bn = (const float*)d_in[14];
    const float* fc2_bn = (const float*)d_in[15];
    float* out = (float*)d_out;

    cudaFuncSetAttribute(mma_lif,  cudaFuncAttributeMaxDynamicSharedMemorySize, SMEM_TOT);
    cudaFuncSetAttribute(mma_gemm, cudaFuncAttributeMaxDynamicSharedMemorySize, SMEM_TOT);

    float *p_xt, *p_xat, *p_A, *p_Bc;
    __nv_bfloat16 *p_sx, *p_qs, *p_h1s, *p_whi, *p_wlo;
    cudaGetSymbolAddress((void**)&p_xt,  g_xt);
    cudaGetSymbolAddress((void**)&p_sx,  g_sx);
    cudaGetSymbolAddress((void**)&p_qs,  g_qs);
    cudaGetSymbolAddress((void**)&p_xat, g_xat);
    cudaGetSymbolAddress((void**)&p_h1s, g_h1s);
    cudaGetSymbolAddress((void**)&p_whi, g_whi);
    cudaGetSymbolAddress((void**)&p_wlo, g_wlo);
    cudaGetSymbolAddress((void**)&p_A,   g_A);
    cudaGetSymbolAddress((void**)&p_Bc,  g_Bc);

    // merged prep: BN fold + weight split (x4) + kvcnt/flag zero + transpose/LIF of x
    prep_kernel<<<5266, 256>>>(q_bn, k_bn, v_bn, proj_bn, fc1_bn, fc2_bn,
                               proj_b, fc1_b, fc2_b,
                               q_w, k_w, v_w, proj_w, fc1_w, fc2_w, x);

    // qkv GEMM + fused LIF + vh: grid (8, 12, 16)
    mma_lif<<<dim3(8, 12, 16), 256, SMEM_TOT>>>(p_sx, CC,
                                                p_whi, p_wlo, W_QKV, CC,
                                                p_A, p_Bc,
                                                nullptr, nullptr,
                                                p_qs, 1536,
                                                out + (long)TBCN);

    // kv counts + fused talking-heads LIF (last-block), then att
    kvcount_kernel<<<1024, 256>>>();
    att_kernel<<<4096, 256>>>();

    // proj GEMM + BN + identity(x) + fused MLP LIF: grid (8, 4, 16)
    mma_lif<<<dim3(8, 4, 16), 256, SMEM_TOT>>>(p_qs, 1536,
                                               p_whi, p_wlo, W_PROJ, CC,
                                               p_A + 1536, p_Bc + 1536,
                                               p_xt, p_xat,
                                               p_sx, CC,
                                               nullptr);

    // fc1 GEMM + fused LIF: grid (8, 16, 16)
    mma_lif<<<dim3(8, 16, 16), 256, SMEM_TOT>>>(p_sx, CC,
                                                p_whi, p_wlo, W_FC1, CC,
                                                p_A + 2048, p_Bc + 2048,
                                                nullptr, nullptr,
                                                p_h1s, HID,
                                                nullptr);

    // fc2 GEMM + BN + idm(x_attn) -> d_out (channel-major)
    mma_gemm<<<dim3(2, 4, 64), 256, SMEM_TOT>>>(p_h1s, (long)NN*HID, HID,
                                                p_whi, p_wlo, W_FC2, HID,
                                                p_A + 4096, p_Bc + 4096, p_xat, (long)NN*CC,
                                                out, (long)CC*NN, CC);
}

// round 16
// speedup vs baseline: 1.0541x; 1.0541x over previous
#include <cuda_runtime.h>
#include <cuda_bf16.h>
#include <cstdint>

// ---------------- problem constants ----------------
#define TT   4
#define BB   16
#define CC   512
#define NN   256
#define HID  2048
#define TBCN (TT*BB*CC*NN)     // 8,388,608

// ---------------- static scratch ----------------
__device__ float         g_xt  [64L*256*512];    // x transposed, channels-last fp32
__device__ __nv_bfloat16 g_sx  [64L*256*512];    // spikes (x / mlp), bf16
__device__ __nv_bfloat16 g_qs  [64L*256*1536];   // qkv spikes bf16 (att in place in q cols)
__device__ float         g_xat [64L*256*512];    // attention block output fp32
__device__ __nv_bfloat16 g_h1s [64L*256*2048];   // fc1 spikes bf16
__device__ __nv_bfloat16 g_kvs [64*512];         // kv spikes bf16
__device__ int           g_kvcnt[64*512];        // kv AND-counts (int, exact)
__device__ __nv_bfloat16 g_whi [3145728];        // weights hi bf16: qkv|proj|fc1|fc2
__device__ __nv_bfloat16 g_wlo [3145728];        // weights lo bf16
__device__ float         g_A   [4608];           // folded BN scale
__device__ float         g_Bc  [4608];           // folded BN bias

#define W_QKV  0L
#define W_PROJ 786432L
#define W_FC1  1048576L
#define W_FC2  2097152L

#define BF1 ((unsigned short)0x3F80)

// ---------------- PTX helpers (baseline ISA only) ----------------
__device__ __forceinline__ uint32_t smem_u32(const void* p) {
    uint32_t a;
    asm("{ .reg .u64 t; cvta.to.shared.u64 t, %1; cvt.u32.u64 %0, t; }" : "=r"(a) : "l"(p));
    return a;
}
__device__ __forceinline__ void cp16(uint32_t dst, const void* src) {
    asm volatile("cp.async.cg.shared.global [%0], [%1], 16;" :: "r"(dst), "l"(src));
}
#define CP_COMMIT() asm volatile("cp.async.commit_group;" ::: "memory")
#define CP_WAIT0()  asm volatile("cp.async.wait_group 0;" ::: "memory")

__device__ __forceinline__ void ldm4(uint32_t& r0, uint32_t& r1, uint32_t& r2, uint32_t& r3,
                                     uint32_t addr) {
    asm volatile("ldmatrix.sync.aligned.m8n8.x4.shared.b16 {%0,%1,%2,%3}, [%4];"
                 : "=r"(r0), "=r"(r1), "=r"(r2), "=r"(r3) : "r"(addr));
}
__device__ __forceinline__ void mma16816(float* c, const uint32_t* a, uint32_t b0, uint32_t b1) {
    asm volatile("mma.sync.aligned.m16n8k16.row.col.f32.bf16.bf16.f32 "
                 "{%0,%1,%2,%3}, {%4,%5,%6,%7}, {%8,%9}, {%0,%1,%2,%3};"
                 : "+f"(c[0]), "+f"(c[1]), "+f"(c[2]), "+f"(c[3])
                 : "r"(a[0]), "r"(a[1]), "r"(a[2]), "r"(a[3]), "r"(b0), "r"(b1));
}
__device__ __forceinline__ unsigned short bfbits(float f) {
    __nv_bfloat16 h = __float2bfloat16(f);
    return *(unsigned short*)&h;
}

// SMEM: per stage A(128x144B) | Bhi(128x144B) | Blo(128x144B); 2 stages; K-chunk 64
#define RS    144
#define STG_A (128*RS)        // 18432
#define STAGE (3*STG_A)       // 55296
#define SMEM_TOT (2*STAGE)    // 110592  (x2 CTAs/SM)

// ---------------- merged prep kernel ----------------
// blocks [0,18): BN fold; [18,3090): weight split (x4 vectorized);
// [3090,3218): zero kvcnt; [3218,5266): transpose + shortcut LIF of x
__global__ void prep_kernel(const float* __restrict__ qbn, const float* __restrict__ kbn,
                            const float* __restrict__ vbn, const float* __restrict__ pbn,
                            const float* __restrict__ f1bn, const float* __restrict__ f2bn,
                            const float* __restrict__ pb, const float* __restrict__ f1b,
                            const float* __restrict__ f2b,
                            const float* __restrict__ qw, const float* __restrict__ kw,
                            const float* __restrict__ vw, const float* __restrict__ pj,
                            const float* __restrict__ f1, const float* __restrict__ f2,
                            const float* __restrict__ x)
{
    int blk = blockIdx.x;
    if (blk < 18) {
        int i = blk * 256 + threadIdx.x;
        if (i >= 4608) return;
        const float* bn; int c; int nc; float bias = 0.f;
        if (i < 1536)      { int s = i >> 9; c = i & 511; nc = CC;
                             bn = (s == 0) ? qbn : (s == 1) ? kbn : vbn; }
        else if (i < 2048) { c = i - 1536; nc = CC;  bn = pbn;  bias = pb[c]; }
        else if (i < 4096) { c = i - 2048; nc = HID; bn = f1bn; bias = f1b[c]; }
        else               { c = i - 4096; nc = CC;  bn = f2bn; bias = f2b[c]; }
        float g  = bn[c];
        float be = bn[nc + c];
        float m  = bn[2*nc + c];
        float v  = bn[3*nc + c];
        float a  = g / sqrtf(v + 1e-5f);
        g_A[i]  = a;
        g_Bc[i] = be + (bias - m) * a;
    } else if (blk < 3090) {
        long i4 = (long)(blk - 18) * 256 + threadIdx.x;   // float4 index, 0..786431
        long i  = i4 * 4;
        float4 w4;
        if (i < 786432L)       { long s = i / 262144L, r = i % 262144L;
                                 const float* src = (s == 0) ? qw : (s == 1) ? kw : vw;
                                 w4 = *(const float4*)(src + r); }
        else if (i < 1048576L) w4 = *(const float4*)(pj + i - 786432L);
        else if (i < 2097152L) w4 = *(const float4*)(f1 + i - 1048576L);
        else                   w4 = *(const float4*)(f2 + i - 2097152L);
        ushort4 hv, lv;
        hv.x = bfbits(w4.x); lv.x = bfbits(w4.x - __bfloat162float(__float2bfloat16(w4.x)));
        hv.y = bfbits(w4.y); lv.y = bfbits(w4.y - __bfloat162float(__float2bfloat16(w4.y)));
        hv.z = bfbits(w4.z); lv.z = bfbits(w4.z - __bfloat162float(__float2bfloat16(w4.z)));
        hv.w = bfbits(w4.w); lv.w = bfbits(w4.w - __bfloat162float(__float2bfloat16(w4.w)));
        *(ushort4*)((unsigned short*)g_whi + i) = hv;
        *(ushort4*)((unsigned short*)g_wlo + i) = lv;
    } else if (blk < 3218) {
        int i = (blk - 3090) * 256 + threadIdx.x;
        g_kvcnt[i] = 0;
    } else {
        __shared__ float t4[4][32][33];
        int idx = blk - 3218;
        int n0 = (idx & 7) * 32;
        int c0 = ((idx >> 3) & 15) * 32;
        int b  = idx >> 7;
        int tx = threadIdx.x & 31, ty = threadIdx.x >> 5;
#pragma unroll
        for (int t = 0; t < TT; t++)
#pragma unroll
            for (int i = 0; i < 4; i++) {
                int c = c0 + ty + i * 8;
                t4[t][ty + i * 8][tx] = x[(((long)t * BB + b) * CC + c) * NN + n0 + tx];
            }
        __syncthreads();
#pragma unroll
        for (int i = 0; i < 4; i++) {
            int n = n0 + ty + i * 8;
            int c = c0 + tx;
            float v = 0.f;
#pragma unroll
            for (int t = 0; t < TT; t++) {
                float xv = t4[t][tx][ty + i * 8];
                long o = (((long)t * BB + b) * NN + n) * CC + c;
                g_xt[o] = xv;
                v = 0.5f * (v + xv);
                bool sp = (v >= 1.0f);
                g_sx[o] = __float2bfloat16(sp ? 1.f : 0.f);
                if (sp) v = 0.f;
            }
        }
    }
}

// coalesced kv AND-count
__global__ void kvcount_kernel()
{
    int tb = blockIdx.x >> 4;
    int ng = blockIdx.x & 15;
    int t  = threadIdx.x;
    const unsigned int* qs = (const unsigned int*)g_qs;
    long base = (long)tb * 256 * 768;
    int c0 = 0, c1 = 0;
#pragma unroll 8
    for (int n = ng * 16; n < ng * 16 + 16; n++) {
        unsigned int k = qs[base + (long)n * 768 + 256 + t];
        unsigned int v = qs[base + (long)n * 768 + 512 + t];
        unsigned int a = k & v;
        c0 += (a & 0xFFFFu) ? 1 : 0;
        c1 += (a >> 16)     ? 1 : 0;
    }
    atomicAdd(&g_kvcnt[tb * 512 + 2 * t],     c0);
    atomicAdd(&g_kvcnt[tb * 512 + 2 * t + 1], c1);
}

// talking-heads LIF over counts (vth=0.5)
__global__ void kvlif2_kernel()
{
    int idx = blockIdx.x * 256 + threadIdx.x;
    int b = idx >> 9, c = idx & 511;
    float v = 0.f;
#pragma unroll
    for (int t = 0; t < TT; t++) {
        int tb = t * BB + b;
        float s = (float)g_kvcnt[tb * 512 + c];
        v = 0.5f * (v + s);
        bool sp = (v >= 0.5f);
        g_kvs[tb * 512 + c] = __float2bfloat16(sp ? 1.f : 0.f);
        if (sp) v = 0.f;
    }
}

// att = q & kv (bitwise over bf16 spike lanes, 8 lanes/thread), in place
__global__ void att_kernel()
{
    long i = (long)blockIdx.x * 256 + threadIdx.x;      // uint4 groups over 64*256*512
    int c8 = (int)(i & 63);
    int n  = (int)((i >> 6) & 255);
    int tb = (int)(i >> 14);
    long qi = (((long)tb * 256 + n) * 1536 + c8 * 8) >> 3;   // uint4 index (8 bf16)
    uint4 q = ((uint4*)g_qs)[qi];
    uint4 kv = ((const uint4*)g_kvs)[((long)tb * 512 + c8 * 8) >> 3];
    q.x &= kv.x; q.y &= kv.y; q.z &= kv.z; q.w &= kv.w;
    ((uint4*)g_qs)[qi] = q;
}

// ---------------- HMMA GEMM with fused LIF epilogue ----------------
// Tile: M = 128 rows = 32 spatial x 4 timesteps, N = 128 channels, grid (NN/32, MC/128, BB).
__global__ void __launch_bounds__(256, 2)
mma_lif(const __nv_bfloat16* __restrict__ A, int lda,
        const __nv_bfloat16* __restrict__ Whi, const __nv_bfloat16* __restrict__ Wlo,
        long wbase, int K,
        const float* __restrict__ Asc, const float* __restrict__ Bsc,
        const float* __restrict__ Res,           // fp32 [tb][n][MC] or null
        float* __restrict__ OutF,                // fp32 [tb][n][MC] or null
        __nv_bfloat16* __restrict__ OutS,        // spikes [tb][n][MC]
        int MC,
        float* __restrict__ vh)                  // fp32 vh or null (qkv only)
{
    extern __shared__ char sm[];
    const uint32_t smb = smem_u32(sm);

    const int tid  = threadIdx.x;
    const int lane = tid & 31;
    const int wid  = tid >> 5;
    const int wm   = wid & 1;
    const int wn   = wid >> 1;
    const int n0   = blockIdx.x * 32;   // spatial
    const int c0   = blockIdx.y * 128;  // channels
    const int b    = blockIdx.z;
    const int nch  = K >> 6;

    const __nv_bfloat16* Ab = A + ((long)b * 256 + n0) * lda;
    const __nv_bfloat16* Hb = Whi + wbase + (long)c0 * K;
    const __nv_bfloat16* Lb = Wlo + wbase + (long)c0 * K;

    const int arow = (lane & 7) + ((lane >> 3) & 1) * 8;
    const int ac8  = (lane >> 4) * 16;
    const int brow = (lane & 7) + (lane >> 4) * 8;
    const int bc8  = ((lane >> 3) & 1) * 16;

    float acc[4][4][4];
#pragma unroll
    for (int a_ = 0; a_ < 4; a_++)
#pragma unroll
        for (int b_ = 0; b_ < 4; b_++)
#pragma unroll
            for (int r_ = 0; r_ < 4; r_++) acc[a_][b_][r_] = 0.f;

    auto load_stage = [&](int s, int kc) {
        uint32_t base = smb + s * STAGE;
#pragma unroll
        for (int jj = 0; jj < 4; jj++) {
            int u = jj * 256 + tid;
            int r = u >> 3, c16 = u & 7;
            long grow = (long)(r >> 5) * 4096 + (r & 31);   // t*BB*256 + nl rows
            cp16(base + r * RS + c16 * 16, Ab + grow * lda + kc * 64 + c16 * 8);
        }
#pragma unroll
        for (int jj = 0; jj < 4; jj++) {
            int u = jj * 256 + tid;
            int r = u >> 3, c16 = u & 7;
            cp16(base + STG_A + r * RS + c16 * 16, Hb + (long)r * K + kc * 64 + c16 * 8);
        }
#pragma unroll
        for (int jj = 0; jj < 4; jj++) {
            int u = jj * 256 + tid;
            int r = u >> 3, c16 = u & 7;
            cp16(base + 2 * STG_A + r * RS + c16 * 16, Lb + (long)r * K + kc * 64 + c16 * 8);
        }
    };

    load_stage(0, 0);
    CP_COMMIT();

    for (int ch = 0; ch < nch; ch++) {
        CP_WAIT0();
        __syncthreads();
        if (ch + 1 < nch) { load_stage((ch + 1) & 1, ch + 1); CP_COMMIT(); }

        const int s = ch & 1;
        const uint32_t ab = smb + s * STAGE;
        const uint32_t hb = ab + STG_A;
        const uint32_t lb = hb + STG_A;

#pragma unroll
        for (int kt = 0; kt < 4; kt++) {
            const int ko = kt * 32;
            uint32_t a[4][4];
#pragma unroll
            for (int mt = 0; mt < 4; mt++)
                ldm4(a[mt][0], a[mt][1], a[mt][2], a[mt][3],
                     ab + (mt * 32 + wm * 16 + arow) * RS + ko + ac8);

            uint32_t bh[8], bl[8];
#pragma unroll
            for (int p = 0; p < 2; p++)
                ldm4(bh[p*4+0], bh[p*4+1], bh[p*4+2], bh[p*4+3],
                     hb + (wn * 32 + p * 16 + brow) * RS + ko + bc8);
#pragma unroll
            for (int g = 0; g < 2; g++) {
                int bi = (g >> 1) * 4 + (g & 1) * 2;
#pragma unroll
                for (int mt = 0; mt < 4; mt++)
                    mma16816(acc[mt][g], a[mt], bh[bi], bh[bi + 1]);
            }
#pragma unroll
            for (int p = 0; p < 2; p++)
                ldm4(bl[p*4+0], bl[p*4+1], bl[p*4+2], bl[p*4+3],
                     lb + (wn * 32 + p * 16 + brow) * RS + ko + bc8);
#pragma unroll
            for (int g = 2; g < 4; g++) {
                int bi = (g >> 1) * 4 + (g & 1) * 2;
#pragma unroll
                for (int mt = 0; mt < 4; mt++)
                    mma16816(acc[mt][g], a[mt], bh[bi], bh[bi + 1]);
            }
#pragma unroll
            for (int g = 0; g < 4; g++) {
                int bi = (g >> 1) * 4 + (g & 1) * 2;
#pragma unroll
                for (int mt = 0; mt < 4; mt++)
                    mma16816(acc[mt][g], a[mt], bl[bi], bl[bi + 1]);
            }
        }
    }

    // ---------------- fused LIF epilogue ----------------
#pragma unroll
    for (int g = 0; g < 4; g++) {
        int col = c0 + wn * 32 + g * 8 + (lane & 3) * 2;
        float sA0 = Asc[col], sA1 = Asc[col + 1];
        float sB0 = Bsc[col], sB1 = Bsc[col + 1];
        bool dv = (vh != nullptr) && (col >= 1024);
        int h = 0, chv = 0;
        if (dv) { h = (col - 1024) >> 6; chv = (col - 1024) & 63; }
#pragma unroll
        for (int rv = 0; rv < 2; rv++) {
            int n = n0 + wm * 16 + (lane >> 2) + rv * 8;
            float v0 = 0.f, v1 = 0.f;
#pragma unroll
            for (int mt = 0; mt < 4; mt++) {
                long rowb = (long)(mt * BB + b) * 256 + n;
                float x0 = acc[mt][g][rv * 2 + 0] * sA0 + sB0;
                float x1 = acc[mt][g][rv * 2 + 1] * sA1 + sB1;
                if (Res) {
                    float2 rr = *(const float2*)(Res + rowb * MC + col);
                    x0 += rr.x; x1 += rr.y;
                }
                if (OutF) {
                    float2 w; w.x = x0; w.y = x1;
                    *(float2*)(OutF + rowb * MC + col) = w;
                }
                v0 = 0.5f * (v0 + x0);
                v1 = 0.5f * (v1 + x1);
                bool s0 = (v0 >= 1.0f), s1 = (v1 >= 1.0f);
                if (s0) v0 = 0.f;
                if (s1) v1 = 0.f;
                ushort2 sp;
                sp.x = s0 ? BF1 : 0;
                sp.y = s1 ? BF1 : 0;
                *(ushort2*)(OutS + rowb * MC + col) = sp;
                if (dv) {
                    float2 vo;
                    vo.x = s0 ? 1.f : 0.f;
                    vo.y = s1 ? 1.f : 0.f;
                    *(float2*)(vh + (((long)(mt * BB + b) * 8 + h) * 256 + n) * 64 + chv) = vo;
                }
            }
        }
    }
}

// ---------------- HMMA GEMM (fc2: channel-major out + residual) ----------------
__global__ void __launch_bounds__(256, 2)
mma_gemm(const __nv_bfloat16* __restrict__ A, long a_bs, int lda,
         const __nv_bfloat16* __restrict__ Whi, const __nv_bfloat16* __restrict__ Wlo,
         long wbase, int K,
         const float* __restrict__ Asc, const float* __restrict__ Bsc,
         const float* __restrict__ Res, long res_bs,
         float* __restrict__ Out, long out_bs, int Mout)
{
    extern __shared__ char sm[];
    const uint32_t smb = smem_u32(sm);

    const int tid  = threadIdx.x;
    const int lane = tid & 31;
    const int wid  = tid >> 5;
    const int wm   = wid & 1;
    const int wn   = wid >> 1;
    const int n0   = blockIdx.x * 128;
    const int c0   = blockIdx.y * 128;
    const int tb   = blockIdx.z;
    const int nch  = K >> 6;

    const __nv_bfloat16* Ab = A + (long)tb * a_bs + (long)n0 * lda;
    const __nv_bfloat16* Hb = Whi + wbase + (long)c0 * K;
    const __nv_bfloat16* Lb = Wlo + wbase + (long)c0 * K;

    const int arow = (lane & 7) + ((lane >> 3) & 1) * 8;
    const int ac8  = (lane >> 4) * 16;
    const int brow = (lane & 7) + (lane >> 4) * 8;
    const int bc8  = ((lane >> 3) & 1) * 16;

    float acc[4][4][4];
#pragma unroll
    for (int a_ = 0; a_ < 4; a_++)
#pragma unroll
        for (int b_ = 0; b_ < 4; b_++)
#pragma unroll
            for (int r_ = 0; r_ < 4; r_++) acc[a_][b_][r_] = 0.f;

    auto load_stage = [&](int s, int kc) {
        uint32_t base = smb + s * STAGE;
#pragma unroll
        for (int jj = 0; jj < 4; jj++) {
            int u = jj * 256 + tid;
            int r = u >> 3, c16 = u & 7;
            cp16(base + r * RS + c16 * 16, Ab + (long)r * lda + kc * 64 + c16 * 8);
        }
#pragma unroll
        for (int jj = 0; jj < 4; jj++) {
            int u = jj * 256 + tid;
            int r = u >> 3, c16 = u & 7;
            cp16(base + STG_A + r * RS + c16 * 16, Hb + (long)r * K + kc * 64 + c16 * 8);
        }
#pragma unroll
        for (int jj = 0; jj < 4; jj++) {
            int u = jj * 256 + tid;
            int r = u >> 3, c16 = u & 7;
            cp16(base + 2 * STG_A + r * RS + c16 * 16, Lb + (long)r * K + kc * 64 + c16 * 8);
        }
    };

    load_stage(0, 0);
    CP_COMMIT();

    for (int ch = 0; ch < nch; ch++) {
        CP_WAIT0();
        __syncthreads();
        if (ch + 1 < nch) { load_stage((ch + 1) & 1, ch + 1); CP_COMMIT(); }

        const int s = ch & 1;
        const uint32_t ab = smb + s * STAGE;
        const uint32_t hb = ab + STG_A;
        const uint32_t lb = hb + STG_A;

#pragma unroll
        for (int kt = 0; kt < 4; kt++) {
            const int ko = kt * 32;
            uint32_t a[4][4];
#pragma unroll
            for (int mt = 0; mt < 4; mt++)
                ldm4(a[mt][0], a[mt][1], a[mt][2], a[mt][3],
                     ab + (wm * 64 + mt * 16 + arow) * RS + ko + ac8);

            uint32_t bh[8], bl[8];
#pragma unroll
            for (int p = 0; p < 2; p++)
                ldm4(bh[p*4+0], bh[p*4+1], bh[p*4+2], bh[p*4+3],
                     hb + (wn * 32 + p * 16 + brow) * RS + ko + bc8);
#pragma unroll
            for (int g = 0; g < 2; g++) {
                int bi = (g >> 1) * 4 + (g & 1) * 2;
#pragma unroll
                for (int mt = 0; mt < 4; mt++)
                    mma16816(acc[mt][g], a[mt], bh[bi], bh[bi + 1]);
            }
#pragma unroll
            for (int p = 0; p < 2; p++)
                ldm4(bl[p*4+0], bl[p*4+1], bl[p*4+2], bl[p*4+3],
                     lb + (wn * 32 + p * 16 + brow) * RS + ko + bc8);
#pragma unroll
            for (int g = 2; g < 4; g++) {
                int bi = (g >> 1) * 4 + (g & 1) * 2;
#pragma unroll
                for (int mt = 0; mt < 4; mt++)
                    mma16816(acc[mt][g], a[mt], bh[bi], bh[bi + 1]);
            }
#pragma unroll
            for (int g = 0; g < 4; g++) {
                int bi = (g >> 1) * 4 + (g & 1) * 2;
#pragma unroll
                for (int mt = 0; mt < 4; mt++)
                    mma16816(acc[mt][g], a[mt], bl[bi], bl[bi + 1]);
            }
        }
    }
    __syncthreads();

    // channel-major epilogue: stage through smem for coalesced stores
    float* sf = (float*)sm;
#pragma unroll
    for (int mt = 0; mt < 4; mt++) {
#pragma unroll
        for (int g = 0; g < 4; g++) {
            int cl = wn * 32 + g * 8 + (lane & 3) * 2;
            int rl = wm * 64 + mt * 16 + (lane >> 2);
            int col = c0 + cl, row = n0 + rl;
            float sA0 = Asc[col], sA1 = Asc[col + 1];
            float sB0 = Bsc[col], sB1 = Bsc[col + 1];
            float v00 = acc[mt][g][0] * sA0 + sB0;
            float v01 = acc[mt][g][1] * sA1 + sB1;
            float v10 = acc[mt][g][2] * sA0 + sB0;
            float v11 = acc[mt][g][3] * sA1 + sB1;
            const float* r0 = Res + (long)tb * res_bs + (long)row * Mout + col;
            float2 ra = *(const float2*)r0;
            float2 rb = *(const float2*)(r0 + 8 * Mout);
            v00 += ra.x; v01 += ra.y; v10 += rb.x; v11 += rb.y;
            sf[cl * 132 + rl]           = v00;
            sf[(cl + 1) * 132 + rl]     = v01;
            sf[cl * 132 + rl + 8]       = v10;
            sf[(cl + 1) * 132 + rl + 8] = v11;
        }
    }
    __syncthreads();
#pragma unroll
    for (int i = 0; i < 16; i++) {
        int c = wid * 16 + i;
        float* orow = Out + (long)tb * out_bs + (long)(c0 + c) * NN + n0;
#pragma unroll
        for (int j = 0; j < 4; j++)
            orow[lane + j * 32] = sf[c * 132 + lane + j * 32];
    }
}

// ---------------- launch ----------------
extern "C" void kernel_launch(void* const* d_in, const int* in_sizes, int n_in,
                              void* d_out, int out_size)
{
    const float* x      = (const float*)d_in[0];
    const float* q_w    = (const float*)d_in[1];
    const float* k_w    = (const float*)d_in[2];
    const float* v_w    = (const float*)d_in[3];
    const float* proj_w = (const float*)d_in[4];
    const float* proj_b = (const float*)d_in[5];
    const float* fc1_w  = (const float*)d_in[6];
    const float* fc1_b  = (const float*)d_in[7];
    const float* fc2_w  = (const float*)d_in[8];
    const float* fc2_b  = (const float*)d_in[9];
    const float* q_bn   = (const float*)d_in[10];
    const float* k_bn   = (const float*)d_in[11];
    const float* v_bn   = (const float*)d_in[12];
    const float* proj_bn= (const float*)d_in[13];
    const float* fc1_bn = (const float*)d_in[14];
    const float* fc2_bn = (const float*)d_in[15];
    float* out = (float*)d_out;

    cudaFuncSetAttribute(mma_lif,  cudaFuncAttributeMaxDynamicSharedMemorySize, SMEM_TOT);
    cudaFuncSetAttribute(mma_gemm, cudaFuncAttributeMaxDynamicSharedMemorySize, SMEM_TOT);

    float *p_xt, *p_xat, *p_A, *p_Bc;
    __nv_bfloat16 *p_sx, *p_qs, *p_h1s, *p_whi, *p_wlo;
    cudaGetSymbolAddress((void**)&p_xt,  g_xt);
    cudaGetSymbolAddress((void**)&p_sx,  g_sx);
    cudaGetSymbolAddress((void**)&p_qs,  g_qs);
    cudaGetSymbolAddress((void**)&p_xat, g_xat);
    cudaGetSymbolAddress((void**)&p_h1s, g_h1s);
    cudaGetSymbolAddress((void**)&p_whi, g_whi);
    cudaGetSymbolAddress((void**)&p_wlo, g_wlo);
    cudaGetSymbolAddress((void**)&p_A,   g_A);
    cudaGetSymbolAddress((void**)&p_Bc,  g_Bc);

    // merged prep: BN fold + weight split (x4) + kvcnt zero + transpose/LIF of x
    prep_kernel<<<5266, 256>>>(q_bn, k_bn, v_bn, proj_bn, fc1_bn, fc2_bn,
                               proj_b, fc1_b, fc2_b,
                               q_w, k_w, v_w, proj_w, fc1_w, fc2_w, x);

    // qkv GEMM + fused LIF + vh: grid (8, 12, 16)
    mma_lif<<<dim3(8, 12, 16), 256, SMEM_TOT>>>(p_sx, CC,
                                                p_whi, p_wlo, W_QKV, CC,
                                                p_A, p_Bc,
                                                nullptr, nullptr,
                                                p_qs, 1536,
                                                out + (long)TBCN);

    kvcount_kernel<<<1024, 256>>>();
    kvlif2_kernel<<<32, 256>>>();
    att_kernel<<<4096, 256>>>();

    // proj GEMM + BN + identity(x) + fused MLP LIF: grid (8, 4, 16)
    mma_lif<<<dim3(8, 4, 16), 256, SMEM_TOT>>>(p_qs, 1536,
                                               p_whi, p_wlo, W_PROJ, CC,
                                               p_A + 1536, p_Bc + 1536,
                                               p_xt, p_xat,
                                               p_sx, CC,
                                               nullptr);

    // fc1 GEMM + fused LIF: grid (8, 16, 16)
    mma_lif<<<dim3(8, 16, 16), 256, SMEM_TOT>>>(p_sx, CC,
                                                p_whi, p_wlo, W_FC1, CC,
                                                p_A + 2048, p_Bc + 2048,
                                                nullptr, nullptr,
                                                p_h1s, HID,
                                                nullptr);

    // fc2 GEMM + BN + idm(x_attn) -> d_out (channel-major)
    mma_gemm<<<dim3(2, 4, 64), 256, SMEM_TOT>>>(p_h1s, (long)NN*HID, HID,
                                                p_whi, p_wlo, W_FC2, HID,
                                                p_A + 4096, p_Bc + 4096, p_xat, (long)NN*CC,
                                                out, (long)CC*NN, CC);
}

// round 17
// speedup vs baseline: 1.0550x; 1.0009x over previous
#include <cuda_runtime.h>
#include <cuda_bf16.h>
#include <cstdint>

// ---------------- problem constants ----------------
#define TT   4
#define BB   16
#define CC   512
#define NN   256
#define HID  2048
#define TBCN (TT*BB*CC*NN)     // 8,388,608

// ---------------- static scratch ----------------
__device__ float         g_xt  [64L*256*512];    // x transposed, channels-last fp32
__device__ __nv_bfloat16 g_sx  [64L*256*512];    // spikes (x / mlp), bf16
__device__ __nv_bfloat16 g_qs  [64L*256*1536];   // qkv spikes bf16 (att in place in q cols)
__device__ float         g_xat [64L*256*512];    // attention block output fp32
__device__ __nv_bfloat16 g_h1s [64L*256*2048];   // fc1 spikes bf16
__device__ int           g_kvcnt[64*512];        // kv AND-counts (int, exact)
__device__ __nv_bfloat16 g_whi [3145728];        // weights hi bf16: qkv|proj|fc1|fc2
__device__ __nv_bfloat16 g_wlo [3145728];        // weights lo bf16
__device__ float         g_A   [4608];           // folded BN scale
__device__ float         g_Bc  [4608];           // folded BN bias

#define W_QKV  0L
#define W_PROJ 786432L
#define W_FC1  1048576L
#define W_FC2  2097152L

#define BF1 ((unsigned short)0x3F80)

// ---------------- PTX helpers (baseline ISA only) ----------------
__device__ __forceinline__ uint32_t smem_u32(const void* p) {
    uint32_t a;
    asm("{ .reg .u64 t; cvta.to.shared.u64 t, %1; cvt.u32.u64 %0, t; }" : "=r"(a) : "l"(p));
    return a;
}
__device__ __forceinline__ void cp16(uint32_t dst, const void* src) {
    asm volatile("cp.async.cg.shared.global [%0], [%1], 16;" :: "r"(dst), "l"(src));
}
#define CP_COMMIT() asm volatile("cp.async.commit_group;" ::: "memory")
#define CP_WAIT0()  asm volatile("cp.async.wait_group 0;" ::: "memory")

__device__ __forceinline__ void ldm4(uint32_t& r0, uint32_t& r1, uint32_t& r2, uint32_t& r3,
                                     uint32_t addr) {
    asm volatile("ldmatrix.sync.aligned.m8n8.x4.shared.b16 {%0,%1,%2,%3}, [%4];"
                 : "=r"(r0), "=r"(r1), "=r"(r2), "=r"(r3) : "r"(addr));
}
__device__ __forceinline__ void mma16816(float* c, const uint32_t* a, uint32_t b0, uint32_t b1) {
    asm volatile("mma.sync.aligned.m16n8k16.row.col.f32.bf16.bf16.f32 "
                 "{%0,%1,%2,%3}, {%4,%5,%6,%7}, {%8,%9}, {%0,%1,%2,%3};"
                 : "+f"(c[0]), "+f"(c[1]), "+f"(c[2]), "+f"(c[3])
                 : "r"(a[0]), "r"(a[1]), "r"(a[2]), "r"(a[3]), "r"(b0), "r"(b1));
}
__device__ __forceinline__ unsigned short bfbits(float f) {
    __nv_bfloat16 h = __float2bfloat16(f);
    return *(unsigned short*)&h;
}

// SMEM: per stage A(128x144B) | Bhi(128x144B) | Blo(128x144B); 2 stages; K-chunk 64
#define RS    144
#define STG_A (128*RS)        // 18432
#define STAGE (3*STG_A)       // 55296
#define SMEM_TOT (2*STAGE)    // 110592  (x2 CTAs/SM)

// ---------------- merged prep kernel ----------------
// blocks [0,18): BN fold; [18,3090): weight split (x4 vectorized);
// [3090,3218): zero kvcnt; [3218,5266): transpose + shortcut LIF of x
__global__ void prep_kernel(const float* __restrict__ qbn, const float* __restrict__ kbn,
                            const float* __restrict__ vbn, const float* __restrict__ pbn,
                            const float* __restrict__ f1bn, const float* __restrict__ f2bn,
                            const float* __restrict__ pb, const float* __restrict__ f1b,
                            const float* __restrict__ f2b,
                            const float* __restrict__ qw, const float* __restrict__ kw,
                            const float* __restrict__ vw, const float* __restrict__ pj,
                            const float* __restrict__ f1, const float* __restrict__ f2,
                            const float* __restrict__ x)
{
    int blk = blockIdx.x;
    if (blk < 18) {
        int i = blk * 256 + threadIdx.x;
        if (i >= 4608) return;
        const float* bn; int c; int nc; float bias = 0.f;
        if (i < 1536)      { int s = i >> 9; c = i & 511; nc = CC;
                             bn = (s == 0) ? qbn : (s == 1) ? kbn : vbn; }
        else if (i < 2048) { c = i - 1536; nc = CC;  bn = pbn;  bias = pb[c]; }
        else if (i < 4096) { c = i - 2048; nc = HID; bn = f1bn; bias = f1b[c]; }
        else               { c = i - 4096; nc = CC;  bn = f2bn; bias = f2b[c]; }
        float g  = bn[c];
        float be = bn[nc + c];
        float m  = bn[2*nc + c];
        float v  = bn[3*nc + c];
        float a  = g / sqrtf(v + 1e-5f);
        g_A[i]  = a;
        g_Bc[i] = be + (bias - m) * a;
    } else if (blk < 3090) {
        long i4 = (long)(blk - 18) * 256 + threadIdx.x;   // float4 index
        long i  = i4 * 4;
        float4 w4;
        if (i < 786432L)       { long s = i / 262144L, r = i % 262144L;
                                 const float* src = (s == 0) ? qw : (s == 1) ? kw : vw;
                                 w4 = *(const float4*)(src + r); }
        else if (i < 1048576L) w4 = *(const float4*)(pj + i - 786432L);
        else if (i < 2097152L) w4 = *(const float4*)(f1 + i - 1048576L);
        else                   w4 = *(const float4*)(f2 + i - 2097152L);
        ushort4 hv, lv;
        hv.x = bfbits(w4.x); lv.x = bfbits(w4.x - __bfloat162float(__float2bfloat16(w4.x)));
        hv.y = bfbits(w4.y); lv.y = bfbits(w4.y - __bfloat162float(__float2bfloat16(w4.y)));
        hv.z = bfbits(w4.z); lv.z = bfbits(w4.z - __bfloat162float(__float2bfloat16(w4.z)));
        hv.w = bfbits(w4.w); lv.w = bfbits(w4.w - __bfloat162float(__float2bfloat16(w4.w)));
        *(ushort4*)((unsigned short*)g_whi + i) = hv;
        *(ushort4*)((unsigned short*)g_wlo + i) = lv;
    } else if (blk < 3218) {
        int i = (blk - 3090) * 256 + threadIdx.x;
        g_kvcnt[i] = 0;
    } else {
        __shared__ float t4[4][32][33];
        int idx = blk - 3218;
        int n0 = (idx & 7) * 32;
        int c0 = ((idx >> 3) & 15) * 32;
        int b  = idx >> 7;
        int tx = threadIdx.x & 31, ty = threadIdx.x >> 5;
#pragma unroll
        for (int t = 0; t < TT; t++)
#pragma unroll
            for (int i = 0; i < 4; i++) {
                int c = c0 + ty + i * 8;
                t4[t][ty + i * 8][tx] = x[(((long)t * BB + b) * CC + c) * NN + n0 + tx];
            }
        __syncthreads();
#pragma unroll
        for (int i = 0; i < 4; i++) {
            int n = n0 + ty + i * 8;
            int c = c0 + tx;
            float v = 0.f;
#pragma unroll
            for (int t = 0; t < TT; t++) {
                float xv = t4[t][tx][ty + i * 8];
                long o = (((long)t * BB + b) * NN + n) * CC + c;
                g_xt[o] = xv;
                v = 0.5f * (v + xv);
                bool sp = (v >= 1.0f);
                g_sx[o] = __float2bfloat16(sp ? 1.f : 0.f);
                if (sp) v = 0.f;
            }
        }
    }
}

// coalesced kv AND-count
__global__ void kvcount_kernel()
{
    int tb = blockIdx.x >> 4;
    int ng = blockIdx.x & 15;
    int t  = threadIdx.x;
    const unsigned int* qs = (const unsigned int*)g_qs;
    long base = (long)tb * 256 * 768;
    int c0 = 0, c1 = 0;
#pragma unroll 8
    for (int n = ng * 16; n < ng * 16 + 16; n++) {
        unsigned int k = qs[base + (long)n * 768 + 256 + t];
        unsigned int v = qs[base + (long)n * 768 + 512 + t];
        unsigned int a = k & v;
        c0 += (a & 0xFFFFu) ? 1 : 0;
        c1 += (a >> 16)     ? 1 : 0;
    }
    atomicAdd(&g_kvcnt[tb * 512 + 2 * t],     c0);
    atomicAdd(&g_kvcnt[tb * 512 + 2 * t + 1], c1);
}

// att with fused talking-heads LIF prologue:
// block = (tb, n-slice of 16); prologue derives kv spikes for this tb's 512 channels
// from g_kvcnt (LIF chain over t' <= t), then ANDs q in place (uint4, 8 bf16 lanes).
__global__ void attkv_kernel()
{
    __shared__ unsigned short kvsp[512];
    int tb = blockIdx.x >> 4;
    int nq = blockIdx.x & 15;
    int t  = tb >> 4;       // tb = tt*BB + b
    int b  = tb & 15;
    int tid = threadIdx.x;

    // prologue: 2 channels per thread, LIF chain to step t
    {
        int c = tid * 2;
        float v0 = 0.f, v1 = 0.f;
        unsigned short s0 = 0, s1 = 0;
#pragma unroll
        for (int tt = 0; tt < TT; tt++) {
            if (tt > t) break;
            int tbb = tt * BB + b;
            float x0 = (float)g_kvcnt[tbb * 512 + c];
            float x1 = (float)g_kvcnt[tbb * 512 + c + 1];
            v0 = 0.5f * (v0 + x0);
            v1 = 0.5f * (v1 + x1);
            bool p0 = (v0 >= 0.5f), p1 = (v1 >= 0.5f);
            if (tt == t) { s0 = p0 ? 0xFFFFu : 0; s1 = p1 ? 0xFFFFu : 0; }
            if (p0) v0 = 0.f;
            if (p1) v1 = 0.f;
        }
        kvsp[c]     = s0;
        kvsp[c + 1] = s1;
    }
    __syncthreads();

    // AND loop: 16 n x 64 c8-groups = 1024 uint4 vectors, 4 per thread
    const uint4* kvv = (const uint4*)kvsp;
#pragma unroll
    for (int it = 0; it < 4; it++) {
        int u  = it * 256 + tid;         // 0..1023
        int c8 = u & 63;
        int n  = nq * 16 + (u >> 6);
        long qi = (((long)tb * 256 + n) * 1536 + c8 * 8) >> 3;
        uint4 q = ((uint4*)g_qs)[qi];
        uint4 m = kvv[c8];
        q.x &= m.x; q.y &= m.y; q.z &= m.z; q.w &= m.w;
        ((uint4*)g_qs)[qi] = q;
    }
}

// ---------------- HMMA GEMM with fused LIF epilogue ----------------
// Tile: M = 128 rows = 32 spatial x 4 timesteps, N = 128 channels, grid (NN/32, MC/128, BB).
__global__ void __launch_bounds__(256, 2)
mma_lif(const __nv_bfloat16* __restrict__ A, int lda,
        const __nv_bfloat16* __restrict__ Whi, const __nv_bfloat16* __restrict__ Wlo,
        long wbase, int K,
        const float* __restrict__ Asc, const float* __restrict__ Bsc,
        const float* __restrict__ Res,           // fp32 [tb][n][MC] or null
        float* __restrict__ OutF,                // fp32 [tb][n][MC] or null
        __nv_bfloat16* __restrict__ OutS,        // spikes [tb][n][MC]
        int MC,
        float* __restrict__ vh)                  // fp32 vh or null (qkv only)
{
    extern __shared__ char sm[];
    const uint32_t smb = smem_u32(sm);

    const int tid  = threadIdx.x;
    const int lane = tid & 31;
    const int wid  = tid >> 5;
    const int wm   = wid & 1;
    const int wn   = wid >> 1;
    const int n0   = blockIdx.x * 32;   // spatial
    const int c0   = blockIdx.y * 128;  // channels
    const int b    = blockIdx.z;
    const int nch  = K >> 6;

    const __nv_bfloat16* Ab = A + ((long)b * 256 + n0) * lda;
    const __nv_bfloat16* Hb = Whi + wbase + (long)c0 * K;
    const __nv_bfloat16* Lb = Wlo + wbase + (long)c0 * K;

    const int arow = (lane & 7) + ((lane >> 3) & 1) * 8;
    const int ac8  = (lane >> 4) * 16;
    const int brow = (lane & 7) + (lane >> 4) * 8;
    const int bc8  = ((lane >> 3) & 1) * 16;

    float acc[4][4][4];
#pragma unroll
    for (int a_ = 0; a_ < 4; a_++)
#pragma unroll
        for (int b_ = 0; b_ < 4; b_++)
#pragma unroll
            for (int r_ = 0; r_ < 4; r_++) acc[a_][b_][r_] = 0.f;

    auto load_stage = [&](int s, int kc) {
        uint32_t base = smb + s * STAGE;
#pragma unroll
        for (int jj = 0; jj < 4; jj++) {
            int u = jj * 256 + tid;
            int r = u >> 3, c16 = u & 7;
            long grow = (long)(r >> 5) * 4096 + (r & 31);   // t*BB*256 + nl rows
            cp16(base + r * RS + c16 * 16, Ab + grow * lda + kc * 64 + c16 * 8);
        }
#pragma unroll
        for (int jj = 0; jj < 4; jj++) {
            int u = jj * 256 + tid;
            int r = u >> 3, c16 = u & 7;
            cp16(base + STG_A + r * RS + c16 * 16, Hb + (long)r * K + kc * 64 + c16 * 8);
        }
#pragma unroll
        for (int jj = 0; jj < 4; jj++) {
            int u = jj * 256 + tid;
            int r = u >> 3, c16 = u & 7;
            cp16(base + 2 * STG_A + r * RS + c16 * 16, Lb + (long)r * K + kc * 64 + c16 * 8);
        }
    };

    load_stage(0, 0);
    CP_COMMIT();

    for (int ch = 0; ch < nch; ch++) {
        CP_WAIT0();
        __syncthreads();
        if (ch + 1 < nch) { load_stage((ch + 1) & 1, ch + 1); CP_COMMIT(); }

        const int s = ch & 1;
        const uint32_t ab = smb + s * STAGE;
        const uint32_t hb = ab + STG_A;
        const uint32_t lb = hb + STG_A;

#pragma unroll
        for (int kt = 0; kt < 4; kt++) {
            const int ko = kt * 32;
            uint32_t a[4][4];
#pragma unroll
            for (int mt = 0; mt < 4; mt++)
                ldm4(a[mt][0], a[mt][1], a[mt][2], a[mt][3],
                     ab + (mt * 32 + wm * 16 + arow) * RS + ko + ac8);

            uint32_t bh[8], bl[8];
#pragma unroll
            for (int p = 0; p < 2; p++)
                ldm4(bh[p*4+0], bh[p*4+1], bh[p*4+2], bh[p*4+3],
                     hb + (wn * 32 + p * 16 + brow) * RS + ko + bc8);
#pragma unroll
            for (int g = 0; g < 2; g++) {
                int bi = (g >> 1) * 4 + (g & 1) * 2;
#pragma unroll
                for (int mt = 0; mt < 4; mt++)
                    mma16816(acc[mt][g], a[mt], bh[bi], bh[bi + 1]);
            }
#pragma unroll
            for (int p = 0; p < 2; p++)
                ldm4(bl[p*4+0], bl[p*4+1], bl[p*4+2], bl[p*4+3],
                     lb + (wn * 32 + p * 16 + brow) * RS + ko + bc8);
#pragma unroll
            for (int g = 2; g < 4; g++) {
                int bi = (g >> 1) * 4 + (g & 1) * 2;
#pragma unroll
                for (int mt = 0; mt < 4; mt++)
                    mma16816(acc[mt][g], a[mt], bh[bi], bh[bi + 1]);
            }
#pragma unroll
            for (int g = 0; g < 4; g++) {
                int bi = (g >> 1) * 4 + (g & 1) * 2;
#pragma unroll
                for (int mt = 0; mt < 4; mt++)
                    mma16816(acc[mt][g], a[mt], bl[bi], bl[bi + 1]);
            }
        }
    }

    // ---------------- fused LIF epilogue ----------------
#pragma unroll
    for (int g = 0; g < 4; g++) {
        int col = c0 + wn * 32 + g * 8 + (lane & 3) * 2;
        float sA0 = Asc[col], sA1 = Asc[col + 1];
        float sB0 = Bsc[col], sB1 = Bsc[col + 1];
        bool dv = (vh != nullptr) && (col >= 1024);
        int h = 0, chv = 0;
        if (dv) { h = (col - 1024) >> 6; chv = (col - 1024) & 63; }
#pragma unroll
        for (int rv = 0; rv < 2; rv++) {
            int n = n0 + wm * 16 + (lane >> 2) + rv * 8;
            float v0 = 0.f, v1 = 0.f;
#pragma unroll
            for (int mt = 0; mt < 4; mt++) {
                long rowb = (long)(mt * BB + b) * 256 + n;
                float x0 = acc[mt][g][rv * 2 + 0] * sA0 + sB0;
                float x1 = acc[mt][g][rv * 2 + 1] * sA1 + sB1;
                if (Res) {
                    float2 rr = *(const float2*)(Res + rowb * MC + col);
                    x0 += rr.x; x1 += rr.y;
                }
                if (OutF) {
                    float2 w; w.x = x0; w.y = x1;
                    *(float2*)(OutF + rowb * MC + col) = w;
                }
                v0 = 0.5f * (v0 + x0);
                v1 = 0.5f * (v1 + x1);
                bool s0 = (v0 >= 1.0f), s1 = (v1 >= 1.0f);
                if (s0) v0 = 0.f;
                if (s1) v1 = 0.f;
                ushort2 sp;
                sp.x = s0 ? BF1 : 0;
                sp.y = s1 ? BF1 : 0;
                *(ushort2*)(OutS + rowb * MC + col) = sp;
                if (dv) {
                    float2 vo;
                    vo.x = s0 ? 1.f : 0.f;
                    vo.y = s1 ? 1.f : 0.f;
                    *(float2*)(vh + (((long)(mt * BB + b) * 8 + h) * 256 + n) * 64 + chv) = vo;
                }
            }
        }
    }
}

// ---------------- HMMA GEMM (fc2: channel-major out + residual) ----------------
__global__ void __launch_bounds__(256, 2)
mma_gemm(const __nv_bfloat16* __restrict__ A, long a_bs, int lda,
         const __nv_bfloat16* __restrict__ Whi, const __nv_bfloat16* __restrict__ Wlo,
         long wbase, int K,
         const float* __restrict__ Asc, const float* __restrict__ Bsc,
         const float* __restrict__ Res, long res_bs,
         float* __restrict__ Out, long out_bs, int Mout)
{
    extern __shared__ char sm[];
    const uint32_t smb = smem_u32(sm);

    const int tid  = threadIdx.x;
    const int lane = tid & 31;
    const int wid  = tid >> 5;
    const int wm   = wid & 1;
    const int wn   = wid >> 1;
    const int n0   = blockIdx.x * 128;
    const int c0   = blockIdx.y * 128;
    const int tb   = blockIdx.z;
    const int nch  = K >> 6;

    const __nv_bfloat16* Ab = A + (long)tb * a_bs + (long)n0 * lda;
    const __nv_bfloat16* Hb = Whi + wbase + (long)c0 * K;
    const __nv_bfloat16* Lb = Wlo + wbase + (long)c0 * K;

    const int arow = (lane & 7) + ((lane >> 3) & 1) * 8;
    const int ac8  = (lane >> 4) * 16;
    const int brow = (lane & 7) + (lane >> 4) * 8;
    const int bc8  = ((lane >> 3) & 1) * 16;

    float acc[4][4][4];
#pragma unroll
    for (int a_ = 0; a_ < 4; a_++)
#pragma unroll
        for (int b_ = 0; b_ < 4; b_++)
#pragma unroll
            for (int r_ = 0; r_ < 4; r_++) acc[a_][b_][r_] = 0.f;

    auto load_stage = [&](int s, int kc) {
        uint32_t base = smb + s * STAGE;
#pragma unroll
        for (int jj = 0; jj < 4; jj++) {
            int u = jj * 256 + tid;
            int r = u >> 3, c16 = u & 7;
            cp16(base + r * RS + c16 * 16, Ab + (long)r * lda + kc * 64 + c16 * 8);
        }
#pragma unroll
        for (int jj = 0; jj < 4; jj++) {
            int u = jj * 256 + tid;
            int r = u >> 3, c16 = u & 7;
            cp16(base + STG_A + r * RS + c16 * 16, Hb + (long)r * K + kc * 64 + c16 * 8);
        }
#pragma unroll
        for (int jj = 0; jj < 4; jj++) {
            int u = jj * 256 + tid;
            int r = u >> 3, c16 = u & 7;
            cp16(base + 2 * STG_A + r * RS + c16 * 16, Lb + (long)r * K + kc * 64 + c16 * 8);
        }
    };

    load_stage(0, 0);
    CP_COMMIT();

    for (int ch = 0; ch < nch; ch++) {
        CP_WAIT0();
        __syncthreads();
        if (ch + 1 < nch) { load_stage((ch + 1) & 1, ch + 1); CP_COMMIT(); }

        const int s = ch & 1;
        const uint32_t ab = smb + s * STAGE;
        const uint32_t hb = ab + STG_A;
        const uint32_t lb = hb + STG_A;

#pragma unroll
        for (int kt = 0; kt < 4; kt++) {
            const int ko = kt * 32;
            uint32_t a[4][4];
#pragma unroll
            for (int mt = 0; mt < 4; mt++)
                ldm4(a[mt][0], a[mt][1], a[mt][2], a[mt][3],
                     ab + (wm * 64 + mt * 16 + arow) * RS + ko + ac8);

            uint32_t bh[8], bl[8];
#pragma unroll
            for (int p = 0; p < 2; p++)
                ldm4(bh[p*4+0], bh[p*4+1], bh[p*4+2], bh[p*4+3],
                     hb + (wn * 32 + p * 16 + brow) * RS + ko + bc8);
#pragma unroll
            for (int g = 0; g < 2; g++) {
                int bi = (g >> 1) * 4 + (g & 1) * 2;
#pragma unroll
                for (int mt = 0; mt < 4; mt++)
                    mma16816(acc[mt][g], a[mt], bh[bi], bh[bi + 1]);
            }
#pragma unroll
            for (int p = 0; p < 2; p++)
                ldm4(bl[p*4+0], bl[p*4+1], bl[p*4+2], bl[p*4+3],
                     lb + (wn * 32 + p * 16 + brow) * RS + ko + bc8);
#pragma unroll
            for (int g = 2; g < 4; g++) {
                int bi = (g >> 1) * 4 + (g & 1) * 2;
#pragma unroll
                for (int mt = 0; mt < 4; mt++)
                    mma16816(acc[mt][g], a[mt], bh[bi], bh[bi + 1]);
            }
#pragma unroll
            for (int g = 0; g < 4; g++) {
                int bi = (g >> 1) * 4 + (g & 1) * 2;
#pragma unroll
                for (int mt = 0; mt < 4; mt++)
                    mma16816(acc[mt][g], a[mt], bl[bi], bl[bi + 1]);
            }
        }
    }
    __syncthreads();

    // channel-major epilogue: stage through smem for coalesced stores
    float* sf = (float*)sm;
#pragma unroll
    for (int mt = 0; mt < 4; mt++) {
#pragma unroll
        for (int g = 0; g < 4; g++) {
            int cl = wn * 32 + g * 8 + (lane & 3) * 2;
            int rl = wm * 64 + mt * 16 + (lane >> 2);
            int col = c0 + cl, row = n0 + rl;
            float sA0 = Asc[col], sA1 = Asc[col + 1];
            float sB0 = Bsc[col], sB1 = Bsc[col + 1];
            float v00 = acc[mt][g][0] * sA0 + sB0;
            float v01 = acc[mt][g][1] * sA1 + sB1;
            float v10 = acc[mt][g][2] * sA0 + sB0;
            float v11 = acc[mt][g][3] * sA1 + sB1;
            const float* r0 = Res + (long)tb * res_bs + (long)row * Mout + col;
            float2 ra = *(const float2*)r0;
            float2 rb = *(const float2*)(r0 + 8 * Mout);
            v00 += ra.x; v01 += ra.y; v10 += rb.x; v11 += rb.y;
            sf[cl * 132 + rl]           = v00;
            sf[(cl + 1) * 132 + rl]     = v01;
            sf[cl * 132 + rl + 8]       = v10;
            sf[(cl + 1) * 132 + rl + 8] = v11;
        }
    }
    __syncthreads();
#pragma unroll
    for (int i = 0; i < 16; i++) {
        int c = wid * 16 + i;
        float* orow = Out + (long)tb * out_bs + (long)(c0 + c) * NN + n0;
#pragma unroll
        for (int j = 0; j < 4; j++)
            orow[lane + j * 32] = sf[c * 132 + lane + j * 32];
    }
}

// ---------------- launch ----------------
extern "C" void kernel_launch(void* const* d_in, const int* in_sizes, int n_in,
                              void* d_out, int out_size)
{
    const float* x      = (const float*)d_in[0];
    const float* q_w    = (const float*)d_in[1];
    const float* k_w    = (const float*)d_in[2];
    const float* v_w    = (const float*)d_in[3];
    const float* proj_w = (const float*)d_in[4];
    const float* proj_b = (const float*)d_in[5];
    const float* fc1_w  = (const float*)d_in[6];
    const float* fc1_b  = (const float*)d_in[7];
    const float* fc2_w  = (const float*)d_in[8];
    const float* fc2_b  = (const float*)d_in[9];
    const float* q_bn   = (const float*)d_in[10];
    const float* k_bn   = (const float*)d_in[11];
    const float* v_bn   = (const float*)d_in[12];
    const float* proj_bn= (const float*)d_in[13];
    const float* fc1_bn = (const float*)d_in[14];
    const float* fc2_bn = (const float*)d_in[15];
    float* out = (float*)d_out;

    cudaFuncSetAttribute(mma_lif,  cudaFuncAttributeMaxDynamicSharedMemorySize, SMEM_TOT);
    cudaFuncSetAttribute(mma_gemm, cudaFuncAttributeMaxDynamicSharedMemorySize, SMEM_TOT);

    float *p_xt, *p_xat, *p_A, *p_Bc;
    __nv_bfloat16 *p_sx, *p_qs, *p_h1s, *p_whi, *p_wlo;
    cudaGetSymbolAddress((void**)&p_xt,  g_xt);
    cudaGetSymbolAddress((void**)&p_sx,  g_sx);
    cudaGetSymbolAddress((void**)&p_qs,  g_qs);
    cudaGetSymbolAddress((void**)&p_xat, g_xat);
    cudaGetSymbolAddress((void**)&p_h1s, g_h1s);
    cudaGetSymbolAddress((void**)&p_whi, g_whi);
    cudaGetSymbolAddress((void**)&p_wlo, g_wlo);
    cudaGetSymbolAddress((void**)&p_A,   g_A);
    cudaGetSymbolAddress((void**)&p_Bc,  g_Bc);

    // merged prep: BN fold + weight split (x4) + kvcnt zero + transpose/LIF of x
    prep_kernel<<<5266, 256>>>(q_bn, k_bn, v_bn, proj_bn, fc1_bn, fc2_bn,
                               proj_b, fc1_b, fc2_b,
                               q_w, k_w, v_w, proj_w, fc1_w, fc2_w, x);

    // qkv GEMM + fused LIF + vh: grid (8, 12, 16)
    mma_lif<<<dim3(8, 12, 16), 256, SMEM_TOT>>>(p_sx, CC,
                                                p_whi, p_wlo, W_QKV, CC,
                                                p_A, p_Bc,
                                                nullptr, nullptr,
                                                p_qs, 1536,
                                                out + (long)TBCN);

    // kv counts, then att with fused talking-heads LIF
    kvcount_kernel<<<1024, 256>>>();
    attkv_kernel<<<1024, 256>>>();

    // proj GEMM + BN + identity(x) + fused MLP LIF: grid (8, 4, 16)
    mma_lif<<<dim3(8, 4, 16), 256, SMEM_TOT>>>(p_qs, 1536,
                                               p_whi, p_wlo, W_PROJ, CC,
                                               p_A + 1536, p_Bc + 1536,
                                               p_xt, p_xat,
                                               p_sx, CC,
                                               nullptr);

    // fc1 GEMM + fused LIF: grid (8, 16, 16)
    mma_lif<<<dim3(8, 16, 16), 256, SMEM_TOT>>>(p_sx, CC,
                                                p_whi, p_wlo, W_FC1, CC,
                                                p_A + 2048, p_Bc + 2048,
                                                nullptr, nullptr,
                                                p_h1s, HID,
                                                nullptr);

    // fc2 GEMM + BN + idm(x_attn) -> d_out (channel-major)
    mma_gemm<<<dim3(2, 4, 64), 256, SMEM_TOT>>>(p_h1s, (long)NN*HID, HID,
                                                p_whi, p_wlo, W_FC2, HID,
                                                p_A + 4096, p_Bc + 4096, p_xat, (long)NN*CC,
                                                out, (long)CC*NN, CC);
}